// round 1
// baseline (speedup 1.0000x reference)
#include <cuda_runtime.h>
#include <math.h>

#define BSZ   16
#define SEQ   48
#define NJ    24
#define NH    8
#define DH    32
#define DIN   256
#define NTOK  (SEQ*NJ)        /* 1152  */
#define MROWS (BSZ*NTOK)      /* 18432 */
#define EPSV  1e-6f

/* scratch: Q, K, V(relu) each [MROWS, DIN] fp32 */
__device__ float g_qkv[3ull * MROWS * DIN];

/* ---------------- projection GEMM: [MROWS,256] @ [256,256] x3 ---------------- */
#define BM 128
#define BN 64
#define BK 16
#define TM 8
#define TN 4

__global__ __launch_bounds__(256) void proj_kernel(
    const float* __restrict__ x,
    const float* __restrict__ Wq, const float* __restrict__ bq,
    const float* __restrict__ Wk, const float* __restrict__ bk,
    const float* __restrict__ Wv, const float* __restrict__ bv)
{
    __shared__ __align__(16) float As[BK][BM + 4];   /* +4 pad: 2-way max conflict, keeps 16B align */
    __shared__ __align__(16) float Bs[BK][BN];

    const int tid  = threadIdx.x;
    const int bm   = blockIdx.x * BM;
    const int wsel = blockIdx.y >> 2;                 /* 0=Q 1=K 2=V */
    const int bn   = (blockIdx.y & 3) * BN;

    const float* W    = (wsel == 0) ? Wq : (wsel == 1 ? Wk : Wv);
    const float* bias = (wsel == 0) ? bq : (wsel == 1 ? bk : bv);
    float* out = g_qkv + (size_t)wsel * MROWS * DIN;

    const int tr = (tid >> 4) * TM;                   /* 16 thread-rows x 8  */
    const int tc = (tid & 15) * TN;                   /* 16 thread-cols x 4  */

    float acc[TM][TN];
#pragma unroll
    for (int i = 0; i < TM; i++)
#pragma unroll
        for (int j = 0; j < TN; j++) acc[i][j] = 0.f;

    for (int k0 = 0; k0 < DIN; k0 += BK) {
#pragma unroll
        for (int i = 0; i < 8; i++) {                 /* A tile 128x16 */
            int idx = i * 256 + tid;
            int r = idx >> 4, c = idx & 15;
            As[c][r] = x[(size_t)(bm + r) * DIN + k0 + c];
        }
#pragma unroll
        for (int i = 0; i < 4; i++) {                 /* B tile 16x64 */
            int idx = i * 256 + tid;
            int r = idx >> 6, c = idx & 63;
            Bs[r][c] = W[(size_t)(k0 + r) * DIN + bn + c];
        }
        __syncthreads();

#pragma unroll
        for (int kk = 0; kk < BK; kk++) {
            float4 b4 = *reinterpret_cast<const float4*>(&Bs[kk][tc]);
            float b[TN] = { b4.x, b4.y, b4.z, b4.w };
            float a[TM];
#pragma unroll
            for (int i = 0; i < TM; i++) a[i] = As[kk][tr + i];
#pragma unroll
            for (int i = 0; i < TM; i++)
#pragma unroll
                for (int j = 0; j < TN; j++)
                    acc[i][j] = fmaf(a[i], b[j], acc[i][j]);
        }
        __syncthreads();
    }

    float bb[TN];
#pragma unroll
    for (int j = 0; j < TN; j++) bb[j] = bias[bn + tc + j];

#pragma unroll
    for (int i = 0; i < TM; i++) {
        float v0 = acc[i][0] + bb[0];
        float v1 = acc[i][1] + bb[1];
        float v2 = acc[i][2] + bb[2];
        float v3 = acc[i][3] + bb[3];
        if (wsel == 2) {                              /* relu on V */
            v0 = fmaxf(v0, 0.f); v1 = fmaxf(v1, 0.f);
            v2 = fmaxf(v2, 0.f); v3 = fmaxf(v3, 0.f);
        }
        float4 o = make_float4(v0, v1, v2, v3);
        *reinterpret_cast<float4*>(&out[(size_t)(bm + tr + i) * DIN + bn + tc]) = o;
    }
}

/* ---------------- per-frame block-diagonal attention ----------------
 * block = (frame, batch); 8 warps, warp h handles head h.
 * smem: q/k/v tiles [24][257] (257 stride -> conflict-free column reads),
 *       per-warp attn scratch [24][25].
 */
#define QK_LD 257
#define AT_LD 25

__global__ __launch_bounds__(256) void attn_kernel(float* __restrict__ out)
{
    extern __shared__ float sm[];
    float* q_s = sm;
    float* k_s = q_s + NJ * QK_LD;
    float* v_s = k_s + NJ * QK_LD;
    float* a_s = v_s + NJ * QK_LD;                    /* [NH][NJ][AT_LD] */

    const int frame = blockIdx.x;
    const int b     = blockIdx.y;
    const int tid   = threadIdx.x;
    const size_t base = ((size_t)b * NTOK + (size_t)frame * NJ) * DIN;

    const float* Q = g_qkv + base;
    const float* K = g_qkv + (size_t)1 * MROWS * DIN + base;
    const float* V = g_qkv + (size_t)2 * MROWS * DIN + base;

    for (int idx = tid; idx < NJ * DIN; idx += 256) { /* coalesced tile load */
        int r = idx >> 8, c = idx & 255;
        q_s[r * QK_LD + c] = Q[(size_t)r * DIN + c];
        k_s[r * QK_LD + c] = K[(size_t)r * DIN + c];
        v_s[r * QK_LD + c] = V[(size_t)r * DIN + c];
    }
    __syncthreads();

    const int h    = tid >> 5;
    const int lane = tid & 31;
    const int ho   = h * DH;
    float* aw = a_s + h * NJ * AT_LD;

    const float scale = 0.17677669529663688f;         /* 1/sqrt(32) */

    /* scores: lane = key index j */
    if (lane < NJ) {
        float kreg[DH];
#pragma unroll
        for (int d = 0; d < DH; d++) kreg[d] = k_s[lane * QK_LD + ho + d];
#pragma unroll
        for (int i = 0; i < NJ; i++) {
            float s = 0.f;
#pragma unroll
            for (int d = 0; d < DH; d++)
                s = fmaf(q_s[i * QK_LD + ho + d], kreg[d], s);   /* q broadcast */
            aw[i * AT_LD + lane] = s * scale;
        }
    }
    __syncwarp();

    /* softmax: lane = query row i ; denominator gets +EPS like the reference */
    if (lane < NJ) {
        float m = -3.402823466e38f;
#pragma unroll
        for (int j = 0; j < NJ; j++) m = fmaxf(m, aw[lane * AT_LD + j]);
        float e[NJ];
        float sum = 0.f;
#pragma unroll
        for (int j = 0; j < NJ; j++) {
            e[j] = expf(aw[lane * AT_LD + j] - m);
            sum += e[j];
        }
        float inv = 1.f / (sum + EPSV);
#pragma unroll
        for (int j = 0; j < NJ; j++) aw[lane * AT_LD + j] = e[j] * inv;
    }
    __syncwarp();

    /* out = attn @ v : lane = dim d */
    {
        const int d = lane;
#pragma unroll
        for (int i = 0; i < NJ; i++) {
            float acc = 0.f;
#pragma unroll
            for (int j = 0; j < NJ; j++)
                acc = fmaf(aw[i * AT_LD + j], v_s[j * QK_LD + ho + d], acc);
            out[base + (size_t)i * DIN + ho + d] = acc;           /* coalesced */
        }
    }
}

extern "C" void kernel_launch(void* const* d_in, const int* in_sizes, int n_in,
                              void* d_out, int out_size)
{
    const float* x  = (const float*)d_in[0];
    const float* Wq = (const float*)d_in[1];
    const float* bq = (const float*)d_in[2];
    const float* Wk = (const float*)d_in[3];
    const float* bk = (const float*)d_in[4];
    const float* Wv = (const float*)d_in[5];
    const float* bv = (const float*)d_in[6];
    float* out = (float*)d_out;

    dim3 g1(MROWS / BM, 12);                          /* 144 x 12 tiles */
    proj_kernel<<<g1, 256>>>(x, Wq, bq, Wk, bk, Wv, bv);

    const int smem = (3 * NJ * QK_LD + NH * NJ * AT_LD) * (int)sizeof(float); /* 93,216 B */
    cudaFuncSetAttribute(attn_kernel, cudaFuncAttributeMaxDynamicSharedMemorySize, smem);
    dim3 g2(SEQ, BSZ);                                /* 48 x 16 frames */
    attn_kernel<<<g2, 256, smem>>>(out);
}

// round 3
// speedup vs baseline: 1.7424x; 1.7424x over previous
#include <cuda_runtime.h>
#include <cuda_bf16.h>
#include <math.h>
#include <stdint.h>

#define BSZ   16
#define NJ    24
#define NH    8
#define DHD   32
#define DIN   256
#define NTOK  1152
#define MROWS 18432        /* BSZ*NTOK */
#define EPSV  1e-6f

/* ---------------- scratch ---------------- */
__device__ __nv_bfloat16 g_xhi[(size_t)MROWS * DIN];
__device__ __nv_bfloat16 g_xlo[(size_t)MROWS * DIN];
__device__ __nv_bfloat16 g_wthi[3 * DIN * DIN];   /* [sel*256+n][k] transposed */
__device__ __nv_bfloat16 g_wtlo[3 * DIN * DIN];
__device__ float g_qkv[3ull * BSZ * NH * NTOK * DHD];   /* [sel*128 + b*8+h][tok][32] */

/* ---------------- conversion: fp32 -> bf16 hi/lo (+ W transpose) -------- */
__global__ __launch_bounds__(256) void cvt_kernel(
    const float* __restrict__ x, const float* __restrict__ Wq,
    const float* __restrict__ Wk, const float* __restrict__ Wv)
{
    int b = blockIdx.x;
    if (b < 4608) {                         /* x: 1,179,648 float4s */
        int idx = b * 256 + threadIdx.x;
        float4 v = ((const float4*)x)[idx];
        float vv[4] = { v.x, v.y, v.z, v.w };
        ushort4 h4, l4;
        unsigned short* hp = &h4.x;
        unsigned short* lp = &l4.x;
#pragma unroll
        for (int c = 0; c < 4; c++) {
            __nv_bfloat16 hb = __float2bfloat16(vv[c]);
            __nv_bfloat16 lb = __float2bfloat16(vv[c] - __bfloat162float(hb));
            hp[c] = __bfloat16_as_ushort(hb);
            lp[c] = __bfloat16_as_ushort(lb);
        }
        ((ushort4*)g_xhi)[idx] = h4;
        ((ushort4*)g_xlo)[idx] = l4;
    } else {                                /* W transpose: 196,608 elems */
        int e = (b - 4608) * 256 + threadIdx.x;
        int ws = e >> 16;
        int r  = e & 65535;
        int n  = r >> 8;
        int k  = r & 255;
        const float* W = (ws == 0) ? Wq : (ws == 1 ? Wk : Wv);
        float v = W[k * 256 + n];
        __nv_bfloat16 hb = __float2bfloat16(v);
        __nv_bfloat16 lb = __float2bfloat16(v - __bfloat162float(hb));
        g_wthi[ws * 65536 + n * 256 + k] = hb;
        g_wtlo[ws * 65536 + n * 256 + k] = lb;
    }
}

/* ---------------- mma.sync bf16x3 GEMM ----------------
 * C[18432, 768] = x[18432,256] @ Wcat^T, Wcat packed [768][256].
 * CTA: 128x128 tile, 8 warps (4x2), warp tile 32x64.
 * K staged in 64-chunks; smem stride 72 bf16 (conflict-free frags).
 */
#define KST 72                       /* smem row stride in bf16 */
#define TILEB (128 * KST)            /* bf16 elems per smem tile */

__device__ __forceinline__ void mma16816(float* c, const uint32_t* a, const uint32_t* b) {
    asm volatile("mma.sync.aligned.m16n8k16.row.col.f32.bf16.bf16.f32 "
        "{%0,%1,%2,%3}, {%4,%5,%6,%7}, {%8,%9}, {%0,%1,%2,%3};"
        : "+f"(c[0]), "+f"(c[1]), "+f"(c[2]), "+f"(c[3])
        : "r"(a[0]), "r"(a[1]), "r"(a[2]), "r"(a[3]), "r"(b[0]), "r"(b[1]));
}

__global__ __launch_bounds__(256) void gemm_kernel(
    const float* __restrict__ bq, const float* __restrict__ bk, const float* __restrict__ bv)
{
    extern __shared__ __nv_bfloat16 sm[];
    __nv_bfloat16* Ah = sm;
    __nv_bfloat16* Al = sm + TILEB;
    __nv_bfloat16* Bh = sm + 2 * TILEB;
    __nv_bfloat16* Bl = sm + 3 * TILEB;

    const int tid  = threadIdx.x;
    const int wid  = tid >> 5, lane = tid & 31;
    const int gid  = lane >> 2, tig = lane & 3;
    const int m0   = blockIdx.x * 128;
    const int n0   = blockIdx.y * 128;
    const int rbase = (wid & 3) * 32;        /* warp m offset */
    const int nbase = (wid >> 2) * 64;       /* warp n offset */

    float c[2][8][4];
#pragma unroll
    for (int mt = 0; mt < 2; mt++)
#pragma unroll
        for (int nt = 0; nt < 8; nt++)
#pragma unroll
            for (int q = 0; q < 4; q++) c[mt][nt][q] = 0.f;

    for (int ch = 0; ch < 4; ch++) {
        const int k0 = ch * 64;
        /* stage A/B hi+lo: 128 rows x 64 bf16 each */
#pragma unroll
        for (int it = 0; it < 4; it++) {
            int idx = it * 256 + tid;
            int r = idx >> 3, g = idx & 7;
            size_t srcA = (size_t)(m0 + r) * 256 + k0 + g * 8;
            size_t srcB = (size_t)(n0 + r) * 256 + k0 + g * 8;
            int dst = r * KST + g * 8;
            *(uint4*)&Ah[dst] = *(const uint4*)&g_xhi[srcA];
            *(uint4*)&Al[dst] = *(const uint4*)&g_xlo[srcA];
            *(uint4*)&Bh[dst] = *(const uint4*)&g_wthi[srcB];
            *(uint4*)&Bl[dst] = *(const uint4*)&g_wtlo[srcB];
        }
        __syncthreads();

#pragma unroll
        for (int ks = 0; ks < 4; ks++) {
            const int kk = ks * 16 + tig * 2;
            uint32_t ah[2][4], al[2][4];
#pragma unroll
            for (int mt = 0; mt < 2; mt++) {
                int ao = (rbase + mt * 16 + gid) * KST + kk;
                ah[mt][0] = *(const uint32_t*)&Ah[ao];
                ah[mt][1] = *(const uint32_t*)&Ah[ao + 8 * KST];
                ah[mt][2] = *(const uint32_t*)&Ah[ao + 8];
                ah[mt][3] = *(const uint32_t*)&Ah[ao + 8 * KST + 8];
                al[mt][0] = *(const uint32_t*)&Al[ao];
                al[mt][1] = *(const uint32_t*)&Al[ao + 8 * KST];
                al[mt][2] = *(const uint32_t*)&Al[ao + 8];
                al[mt][3] = *(const uint32_t*)&Al[ao + 8 * KST + 8];
            }
#pragma unroll
            for (int nt = 0; nt < 8; nt++) {
                int bo = (nbase + nt * 8 + gid) * KST + kk;
                uint32_t bh2[2], bl2[2];
                bh2[0] = *(const uint32_t*)&Bh[bo];
                bh2[1] = *(const uint32_t*)&Bh[bo + 8];
                bl2[0] = *(const uint32_t*)&Bl[bo];
                bl2[1] = *(const uint32_t*)&Bl[bo + 8];
#pragma unroll
                for (int mt = 0; mt < 2; mt++) {
                    mma16816(c[mt][nt], ah[mt], bh2);   /* hi*hi */
                    mma16816(c[mt][nt], ah[mt], bl2);   /* hi*lo */
                    mma16816(c[mt][nt], al[mt], bh2);   /* lo*hi */
                }
            }
        }
        __syncthreads();
    }

    /* epilogue: bias (+relu on V), write head-major
     * n0 blocks: {0,128}->Q, {256,384}->K, {512,640}->V; 128-row m tiles stay in one batch */
    const int sel = n0 >> 8;
    const float* bias = (sel == 0) ? bq : (sel == 1 ? bk : bv);
    const int bb = m0 / NTOK;
    const int tokbase = m0 % NTOK;
    float* outsel = g_qkv + ((size_t)(sel * 128 + bb * 8)) * NTOK * DHD;

#pragma unroll
    for (int mt = 0; mt < 2; mt++) {
        int r0 = tokbase + rbase + mt * 16 + gid;   /* tok of c0/c1 */
#pragma unroll
        for (int nt = 0; nt < 8; nt++) {
            int cn = (n0 & 255) + nbase + nt * 8 + tig * 2;
            int h = cn >> 5, d = cn & 31;
            float bi0 = bias[cn], bi1 = bias[cn + 1];
            float v0 = c[mt][nt][0] + bi0, v1 = c[mt][nt][1] + bi1;
            float v2 = c[mt][nt][2] + bi0, v3 = c[mt][nt][3] + bi1;
            if (sel == 2) {
                v0 = fmaxf(v0, 0.f); v1 = fmaxf(v1, 0.f);
                v2 = fmaxf(v2, 0.f); v3 = fmaxf(v3, 0.f);
            }
            float* p0 = outsel + ((size_t)h * NTOK + r0) * DHD + d;
            *(float2*)p0 = make_float2(v0, v1);
            *(float2*)(p0 + 8 * DHD) = make_float2(v2, v3);   /* row +8 */
        }
    }
}

/* ---------------- attention: warp per (b, h, frame) ----------------
 * qkv layout [sel*128+b*8+h][tok][32]; per-warp smem scratch 32x28 floats,
 * reused for q^T (phase 1) then attn^T (phase 3). Softmax via shuffles.
 */
#define SWST 28

__global__ __launch_bounds__(256) void attn_kernel(float* __restrict__ out)
{
    __shared__ float sw[8 * 32 * SWST];     /* 28 KB */
    const int bh   = blockIdx.x;            /* 0..127 */
    const int wid  = threadIdx.x >> 5;
    const int lane = threadIdx.x & 31;
    const int frame = blockIdx.y * 8 + wid; /* 0..47 */

    const float* qb = g_qkv + ((size_t)bh * NTOK + (size_t)frame * NJ) * DHD;
    const float* kb = g_qkv + ((size_t)(128 + bh) * NTOK + (size_t)frame * NJ) * DHD;
    const float* vb = g_qkv + ((size_t)(256 + bh) * NTOK + (size_t)frame * NJ) * DHD;

    float* sc = sw + wid * 32 * SWST;

    /* stage q transposed: sc[d][i] = q[i][d] */
#pragma unroll
    for (int r = 0; r < NJ; r++)
        sc[lane * SWST + r] = qb[r * DHD + lane];
    __syncwarp();

    /* phase 1: lane j holds K row; s[i] = q_i . k_j */
    const int j = (lane < NJ) ? lane : 0;
    float kreg[DHD];
    {
        const float4* kp = (const float4*)(kb + j * DHD);
#pragma unroll
        for (int cc = 0; cc < 8; cc++) {
            float4 kk = kp[cc];
            kreg[4*cc] = kk.x; kreg[4*cc+1] = kk.y; kreg[4*cc+2] = kk.z; kreg[4*cc+3] = kk.w;
        }
    }
    float s[NJ];
#pragma unroll
    for (int i = 0; i < NJ; i++) s[i] = 0.f;
#pragma unroll
    for (int d = 0; d < DHD; d++) {
        float kd = kreg[d];
#pragma unroll
        for (int i4 = 0; i4 < 6; i4++) {
            float4 q4 = *(const float4*)&sc[d * SWST + i4 * 4];
            s[i4*4+0] = fmaf(q4.x, kd, s[i4*4+0]);
            s[i4*4+1] = fmaf(q4.y, kd, s[i4*4+1]);
            s[i4*4+2] = fmaf(q4.z, kd, s[i4*4+2]);
            s[i4*4+3] = fmaf(q4.w, kd, s[i4*4+3]);
        }
    }
    const float scale = 0.17677669529663688f;   /* 1/sqrt(32) */
#pragma unroll
    for (int i = 0; i < NJ; i++)
        s[i] = (lane < NJ) ? s[i] * scale : -3.402823466e38f;

    /* softmax over j (lanes); eps in denominator like reference */
    __syncwarp();
    float w_[NJ];
#pragma unroll
    for (int i = 0; i < NJ; i++) {
        float m = s[i];
#pragma unroll
        for (int off = 16; off > 0; off >>= 1)
            m = fmaxf(m, __shfl_xor_sync(0xffffffffu, m, off));
        float e = __expf(s[i] - m);             /* masked lanes -> 0 */
        float sum = e;
#pragma unroll
        for (int off = 16; off > 0; off >>= 1)
            sum += __shfl_xor_sync(0xffffffffu, sum, off);
        w_[i] = e / (sum + EPSV);
    }

    /* store attn transposed: sc[j][i] = w(i,j) */
    if (lane < NJ) {
#pragma unroll
        for (int i = 0; i < NJ; i++)
            sc[lane * SWST + i] = w_[i];
    }
    __syncwarp();

    /* phase 3: lane = d; o[i][d] = sum_j w(i,j) v[j][d] */
    float vreg[NJ];
#pragma unroll
    for (int jj = 0; jj < NJ; jj++)
        vreg[jj] = vb[jj * DHD + lane];
    float o[NJ];
#pragma unroll
    for (int i = 0; i < NJ; i++) o[i] = 0.f;
#pragma unroll
    for (int jj = 0; jj < NJ; jj++) {
        float vj = vreg[jj];
#pragma unroll
        for (int i4 = 0; i4 < 6; i4++) {
            float4 a4 = *(const float4*)&sc[jj * SWST + i4 * 4];
            o[i4*4+0] = fmaf(a4.x, vj, o[i4*4+0]);
            o[i4*4+1] = fmaf(a4.y, vj, o[i4*4+1]);
            o[i4*4+2] = fmaf(a4.z, vj, o[i4*4+2]);
            o[i4*4+3] = fmaf(a4.w, vj, o[i4*4+3]);
        }
    }

    /* out[b][tok][h*32+d] */
    const int b = bh >> 3, h = bh & 7;
    float* od = out + ((size_t)b * NTOK + (size_t)frame * NJ) * DIN + h * DHD + lane;
#pragma unroll
    for (int i = 0; i < NJ; i++)
        od[(size_t)i * DIN] = o[i];
}

/* ---------------- launch ---------------- */
extern "C" void kernel_launch(void* const* d_in, const int* in_sizes, int n_in,
                              void* d_out, int out_size)
{
    const float* x  = (const float*)d_in[0];
    const float* Wq = (const float*)d_in[1];
    const float* bq = (const float*)d_in[2];
    const float* Wk = (const float*)d_in[3];
    const float* bk = (const float*)d_in[4];
    const float* Wv = (const float*)d_in[5];
    const float* bv = (const float*)d_in[6];
    float* out = (float*)d_out;

    cvt_kernel<<<4608 + 768, 256>>>(x, Wq, Wk, Wv);

    const int smem = 4 * TILEB * (int)sizeof(__nv_bfloat16);   /* 73,728 B */
    cudaFuncSetAttribute(gemm_kernel, cudaFuncAttributeMaxDynamicSharedMemorySize, smem);
    gemm_kernel<<<dim3(144, 6), 256, smem>>>(bq, bk, bv);

    attn_kernel<<<dim3(128, 6), 256>>>(out);
}